// round 1
// baseline (speedup 1.0000x reference)
#include <cuda_runtime.h>
#include <cuda_bf16.h>
#include <math.h>

#define L_SEQ 2049
#define BATCH 8
#define NH 16
#define HD 64
#define NS 128
#define DIN 1024
#define CONVD 1280
#define DPROJ 2320
#define NROWS 2056
#define GENEF 384
#define DMODEL 512

// ------------------------- scratch (static device globals) -------------------
__device__ float d_feat[NROWS * GENEF];
__device__ float d_X[NROWS * DMODEL];
__device__ float d_Z[2][NROWS * DPROJ];
__device__ float d_xBC[2][(size_t)BATCH * L_SEQ * CONVD];
__device__ float d_dt[2][BATCH * L_SEQ * NH];
__device__ float d_dA[2][BATCH * L_SEQ * NH];
__device__ float d_y[2][(size_t)BATCH * L_SEQ * DIN];
__device__ float d_weff[2][DIN];

__device__ __forceinline__ int seq_row(int b, int t) {
    return (t == 0) ? (2048 + b) : (t - 1);
}

// ------------------------- 1. feature rows (2056 x 384) ----------------------
__global__ void feat_kernel(const int* __restrict__ pidx,
                            const int* __restrict__ chridx,
                            const float* __restrict__ locus_fourier,
                            const float* __restrict__ pathway,
                            const float* __restrict__ pert_emb,
                            const float* __restrict__ gene_id,
                            const float* __restrict__ chr_emb,
                            const float* __restrict__ locus_w,
                            const float* __restrict__ locus_b,
                            const float* __restrict__ cond_w,
                            const float* __restrict__ cond_b) {
    int g = blockIdx.x;
    int tid = threadIdx.x;  // 128 threads
    if (g < 2048) {
        d_feat[g * GENEF + tid] = gene_id[g * 128 + tid];
        d_feat[g * GENEF + 128 + tid] = pathway[g * 128 + tid];
        if (tid < 64) {
            int ci = chridx[g];
            d_feat[g * GENEF + 256 + tid] = chr_emb[ci * 64 + tid];
        } else {
            int j = tid - 64;
            float acc = locus_b[j];
            const float* lf = locus_fourier + g * 64;
            const float* lw = locus_w + j * 64;
            for (int k = 0; k < 64; k++) acc = fmaf(lf[k], lw[k], acc);
            // exact GELU
            float ge = 0.5f * acc * (1.f + erff(acc * 0.70710678118654752f));
            d_feat[g * GENEF + 320 + j] = ge;
        }
    } else {
        int b = g - 2048;
        const float* pe = pert_emb + (size_t)pidx[b] * 128;
        for (int j = tid; j < GENEF; j += 128) {
            float acc = cond_b[j];
            const float* cw = cond_w + (size_t)j * 128;
            for (int k = 0; k < 128; k++) acc = fmaf(pe[k], cw[k], acc);
            d_feat[g * GENEF + j] = acc;
        }
    }
}

// ------------------------- 2. SGEMM: C = A @ W^T (+bias) ---------------------
// A selected by src_sel (0: d_feat, 1: d_X), C by dst_sel (0: d_X, 1/2: d_Z[0/1])
__global__ __launch_bounds__(256) void sgemm_kernel(int src_sel,
                                                    const float* __restrict__ W,
                                                    const float* __restrict__ bias,
                                                    int dst_sel, int M, int N, int K) {
    const float* A = (src_sel == 0) ? d_feat : d_X;
    float* C = (dst_sel == 0) ? d_X : d_Z[dst_sel - 1];

    __shared__ float As[16][65];
    __shared__ float Ws[16][65];
    int tid = threadIdx.x;
    int tx = tid & 15, ty = tid >> 4;
    int row0 = blockIdx.y * 64;
    int col0 = blockIdx.x * 64;
    float acc[4][4] = {};

    int lm = tid >> 2;        // 0..63
    int lk = (tid & 3) * 4;   // 0,4,8,12

    for (int k0 = 0; k0 < K; k0 += 16) {
        int ar = row0 + lm;
        if (ar < M) {
            const float* ap = A + (size_t)ar * K + k0 + lk;
#pragma unroll
            for (int j = 0; j < 4; j++) As[lk + j][lm] = ap[j];
        } else {
#pragma unroll
            for (int j = 0; j < 4; j++) As[lk + j][lm] = 0.f;
        }
        int wr = col0 + lm;
        if (wr < N) {
            const float* wp = W + (size_t)wr * K + k0 + lk;
#pragma unroll
            for (int j = 0; j < 4; j++) Ws[lk + j][lm] = wp[j];
        } else {
#pragma unroll
            for (int j = 0; j < 4; j++) Ws[lk + j][lm] = 0.f;
        }
        __syncthreads();
#pragma unroll
        for (int k = 0; k < 16; k++) {
            float ra[4], rb[4];
#pragma unroll
            for (int i = 0; i < 4; i++) ra[i] = As[k][ty * 4 + i];
#pragma unroll
            for (int i = 0; i < 4; i++) rb[i] = Ws[k][tx * 4 + i];
#pragma unroll
            for (int i = 0; i < 4; i++)
#pragma unroll
                for (int j = 0; j < 4; j++)
                    acc[i][j] = fmaf(ra[i], rb[j], acc[i][j]);
        }
        __syncthreads();
    }
#pragma unroll
    for (int i = 0; i < 4; i++) {
        int r = row0 + ty * 4 + i;
        if (r >= M) continue;
#pragma unroll
        for (int j = 0; j < 4; j++) {
            int c = col0 + tx * 4 + j;
            if (c < N) C[(size_t)r * N + c] = acc[i][j] + (bias ? bias[c] : 0.f);
        }
    }
}

// ------------------------- 3. causal depthwise conv + silu -------------------
__global__ void conv_kernel(const float* __restrict__ cw_f, const float* __restrict__ cb_f,
                            const float* __restrict__ cw_b, const float* __restrict__ cb_b) {
    int t = blockIdx.x;    // 0..2048
    int b = blockIdx.y;    // 0..7
    int dir = blockIdx.z;  // 0 fwd, 1 bwd
    const float* Z = d_Z[dir];
    const float* cw = dir ? cw_b : cw_f;
    const float* cb = dir ? cb_b : cb_f;
    float* dst = d_xBC[dir] + ((size_t)(b * L_SEQ + t)) * CONVD;

    const float* rows[4];
#pragma unroll
    for (int k = 0; k < 4; k++) {
        int tau = dir ? (t + 3 - k) : (t - 3 + k);
        const float* rp = nullptr;
        if (tau >= 0 && tau < L_SEQ)
            rp = Z + (size_t)seq_row(b, tau) * DPROJ + DIN;  // xBC channels start at 1024
        rows[k] = rp;
    }
    for (int c = threadIdx.x; c < CONVD; c += blockDim.x) {
        float acc = cb[c];
#pragma unroll
        for (int k = 0; k < 4; k++)
            if (rows[k]) acc = fmaf(rows[k][c], cw[c * 4 + k], acc);
        dst[c] = acc / (1.f + expf(-acc));  // silu
    }
}

// ------------------------- 4. dt / dA ----------------------------------------
__global__ void dtda_kernel(const float* __restrict__ fdtb, const float* __restrict__ fAl,
                            const float* __restrict__ bdtb, const float* __restrict__ bAl) {
    int idx = blockIdx.x * blockDim.x + threadIdx.x;
    const int per = BATCH * L_SEQ * NH;
    if (idx >= 2 * per) return;
    int dir = idx / per;
    int r = idx % per;
    int h = r & 15;
    int bt = r >> 4;  // b*L + t
    int t = bt % L_SEQ;
    int b = bt / L_SEQ;
    int row = seq_row(b, t);
    float raw = d_Z[dir][(size_t)row * DPROJ + (DIN + CONVD) + h] + (dir ? bdtb : fdtb)[h];
    float dtv = (raw > 20.f) ? raw : log1pf(expf(raw));
    float Al = (dir ? bAl : fAl)[h];
    float dAv = expf(-expf(Al) * dtv);
    d_dt[dir][bt * NH + h] = dtv;
    d_dA[dir][bt * NH + h] = dAv;
}

// ------------------------- 5. effective output vector ------------------------
__global__ void weff_kernel(const float* __restrict__ head_w,
                            const float* __restrict__ fow,
                            const float* __restrict__ bow) {
    int idx = blockIdx.x * blockDim.x + threadIdx.x;
    if (idx >= 2 * DIN) return;
    int dir = idx >> 10;
    int j = idx & 1023;
    const float* ow = dir ? bow : fow;
    float acc = 0.f;
    for (int i = 0; i < DMODEL; i++) acc = fmaf(ow[(size_t)i * DIN + j], head_w[i], acc);
    d_weff[dir][j] = acc;
}

// ------------------------- 6. sequential SSM scan ----------------------------
// block = (dir, b, h); 128 threads; thread owns p = tid&63, n-range = (tid>>6)*64..+63
__global__ __launch_bounds__(128) void scan_kernel(const float* __restrict__ fD,
                                                   const float* __restrict__ bD) {
    int blk = blockIdx.x;     // 0..255
    int dir = blk >> 7;
    int bh = blk & 127;
    int b = bh >> 4;
    int h = bh & 15;
    const float* xBC = d_xBC[dir];
    const float* dtp = d_dt[dir];
    const float* dAp = d_dA[dir];
    float* yp = d_y[dir];
    float Dh = (dir ? bD : fD)[h];

    int tid = threadIdx.x;
    int p = tid & 63;
    int nh = tid >> 6;

    float hs[64];
#pragma unroll
    for (int i = 0; i < 64; i++) hs[i] = 0.f;

    __shared__ float sB[128], sC[128], sx[64], sred[128];

    for (int s = 0; s < L_SEQ; s++) {
        int t = dir ? (L_SEQ - 1 - s) : s;
        size_t rb = (size_t)(b * L_SEQ + t);
        const float* base = xBC + rb * CONVD;
        sB[tid] = base[DIN + tid];
        sC[tid] = base[DIN + NS + tid];
        if (tid < 64) sx[tid] = base[h * HD + tid];
        __syncthreads();
        float dAv = dAp[rb * NH + h];
        float coef = dtp[rb * NH + h] * sx[p];
        const float* Bp = sB + nh * 64;
        const float* Cp = sC + nh * 64;
        float a0 = 0.f, a1 = 0.f, a2 = 0.f, a3 = 0.f;
#pragma unroll
        for (int n = 0; n < 64; n += 4) {
            hs[n]     = fmaf(dAv, hs[n],     coef * Bp[n]);
            a0 = fmaf(hs[n],     Cp[n],     a0);
            hs[n + 1] = fmaf(dAv, hs[n + 1], coef * Bp[n + 1]);
            a1 = fmaf(hs[n + 1], Cp[n + 1], a1);
            hs[n + 2] = fmaf(dAv, hs[n + 2], coef * Bp[n + 2]);
            a2 = fmaf(hs[n + 2], Cp[n + 2], a2);
            hs[n + 3] = fmaf(dAv, hs[n + 3], coef * Bp[n + 3]);
            a3 = fmaf(hs[n + 3], Cp[n + 3], a3);
        }
        sred[tid] = (a0 + a1) + (a2 + a3);
        __syncthreads();
        if (tid < 64) {
            float yv = sred[tid] + sred[tid + 64] + Dh * sx[tid];
            yp[(rb * NH + h) * HD + tid] = yv;
        }
        __syncthreads();
    }
}

// ------------------------- 7. gate + RMSnorm + fused head --------------------
__global__ void final_kernel(const float* __restrict__ fnw, const float* __restrict__ bnw,
                             const float* __restrict__ head_b, float* __restrict__ out) {
    int blk = blockIdx.x;       // 0 .. 8*2048-1
    int b = blk >> 11;
    int t = (blk & 2047) + 1;   // t in [1, 2048]
    int tid = threadIdx.x;      // 256
    __shared__ float s1[256], s2[256];
    int zrow = t - 1;           // gene row (t>=1)
    float resv = 0.f;
    for (int dir = 0; dir < 2; dir++) {
        const float* y = d_y[dir] + ((size_t)(b * L_SEQ) + t) * DIN;
        const float* z = d_Z[dir] + (size_t)zrow * DPROJ;  // z = first 1024 cols
        const float* nw = dir ? bnw : fnw;
        const float* we = d_weff[dir];
        float ssq = 0.f, sdot = 0.f;
        for (int j = tid; j < DIN; j += 256) {
            float zz = z[j];
            float g = y[j] * (zz / (1.f + expf(-zz)));
            ssq = fmaf(g, g, ssq);
            sdot = fmaf(g, nw[j] * we[j], sdot);
        }
        __syncthreads();
        s1[tid] = ssq;
        s2[tid] = sdot;
        __syncthreads();
        for (int off = 128; off; off >>= 1) {
            if (tid < off) {
                s1[tid] += s1[tid + off];
                s2[tid] += s2[tid + off];
            }
            __syncthreads();
        }
        if (tid == 0)
            resv += rsqrtf(s1[0] * (1.f / 1024.f) + 1e-5f) * s2[0];
    }
    if (tid == 0) out[blk] = resv + head_b[0];
}

// ------------------------- launch --------------------------------------------
extern "C" void kernel_launch(void* const* d_in, const int* in_sizes, int n_in,
                              void* d_out, int out_size) {
    const int* pidx            = (const int*)d_in[0];
    const int* chridx          = (const int*)d_in[1];
    const float* locus_fourier = (const float*)d_in[2];
    const float* pathway       = (const float*)d_in[3];
    const float* pert_emb      = (const float*)d_in[4];
    const float* gene_id       = (const float*)d_in[5];
    const float* chr_emb       = (const float*)d_in[6];
    const float* locus_w       = (const float*)d_in[7];
    const float* locus_b       = (const float*)d_in[8];
    const float* cond_w        = (const float*)d_in[9];
    const float* cond_b        = (const float*)d_in[10];
    const float* in_w          = (const float*)d_in[11];
    const float* in_b          = (const float*)d_in[12];
    const float* head_w        = (const float*)d_in[13];
    const float* head_b        = (const float*)d_in[14];
    const float* f_in_w        = (const float*)d_in[15];
    const float* f_conv_w      = (const float*)d_in[16];
    const float* f_conv_b      = (const float*)d_in[17];
    const float* f_dt_bias     = (const float*)d_in[18];
    const float* f_A_log       = (const float*)d_in[19];
    const float* f_D           = (const float*)d_in[20];
    const float* f_norm_w      = (const float*)d_in[21];
    const float* f_out_w       = (const float*)d_in[22];
    const float* b_in_w        = (const float*)d_in[23];
    const float* b_conv_w      = (const float*)d_in[24];
    const float* b_conv_b      = (const float*)d_in[25];
    const float* b_dt_bias     = (const float*)d_in[26];
    const float* b_A_log       = (const float*)d_in[27];
    const float* b_D           = (const float*)d_in[28];
    const float* b_norm_w      = (const float*)d_in[29];
    const float* b_out_w       = (const float*)d_in[30];
    float* out = (float*)d_out;

    // 1. feature rows
    feat_kernel<<<NROWS, 128>>>(pidx, chridx, locus_fourier, pathway, pert_emb,
                                gene_id, chr_emb, locus_w, locus_b, cond_w, cond_b);

    // 2. X = feat @ in_w^T + in_b  (2056 x 512)
    {
        dim3 g((DMODEL + 63) / 64, (NROWS + 63) / 64);
        sgemm_kernel<<<g, 256>>>(0, in_w, in_b, 0, NROWS, DMODEL, GENEF);
    }
    // 3. Z_dir = X @ {f,b}_in_w^T   (2056 x 2320)
    {
        dim3 g((DPROJ + 63) / 64, (NROWS + 63) / 64);
        sgemm_kernel<<<g, 256>>>(1, f_in_w, nullptr, 1, NROWS, DPROJ, DMODEL);
        sgemm_kernel<<<g, 256>>>(1, b_in_w, nullptr, 2, NROWS, DPROJ, DMODEL);
    }
    // 4. depthwise conv + silu (both dirs)
    {
        dim3 g(L_SEQ, BATCH, 2);
        conv_kernel<<<g, 256>>>(f_conv_w, f_conv_b, b_conv_w, b_conv_b);
    }
    // 5. dt / dA
    {
        int tot = 2 * BATCH * L_SEQ * NH;
        dtda_kernel<<<(tot + 255) / 256, 256>>>(f_dt_bias, f_A_log, b_dt_bias, b_A_log);
    }
    // 6. w_eff = out_w^T @ head_w^T
    weff_kernel<<<(2 * DIN + 255) / 256, 256>>>(head_w, f_out_w, b_out_w);

    // 7. sequential scan (both dirs concurrently)
    scan_kernel<<<256, 128>>>(f_D, b_D);

    // 8. gate + RMSnorm + fused output head
    final_kernel<<<BATCH * 2048, 256>>>(f_norm_w, b_norm_w, head_b, out);
}

// round 2
// speedup vs baseline: 1.5315x; 1.5315x over previous
#include <cuda_runtime.h>
#include <cuda_bf16.h>
#include <math.h>

#define L_SEQ 2049
#define BATCH 8
#define NH 16
#define HD 64
#define NS 128
#define DIN 1024
#define CONVD 1280
#define DPROJ 2320
#define NROWS 2056
#define GENEF 384
#define DMODEL 512

// ------------------------- scratch (static device globals) -------------------
__device__ float d_feat[NROWS * GENEF];
__device__ float d_X[NROWS * DMODEL];
__device__ float d_Z[2][NROWS * DPROJ];
__device__ float d_xBCs[2][(size_t)L_SEQ * CONVD];       // batch-shared conv out (valid t>=4)
__device__ float d_xBC0[2][BATCH * 4 * CONVD];           // per-batch conv out, t in 0..3
__device__ float d_dtr[2][NROWS * NH];                   // per-row dt
__device__ float d_dAr[2][NROWS * NH];                   // per-row dA
__device__ float d_yp[2][(size_t)BATCH * L_SEQ * NH * 128];  // y partials (2 halves of n)
__device__ float d_P[2][(size_t)2048 * DIN];             // silu(z) per gene row
__device__ float d_wcomb[2][DIN];                        // norm_w * (out_w^T @ head_w)

__device__ __forceinline__ int seq_row(int b, int t) {
    return (t == 0) ? (2048 + b) : (t - 1);
}
__device__ __forceinline__ const float* xbc_ptr(int dir, int b, int t) {
    return (t >= 4) ? (d_xBCs[dir] + (size_t)t * CONVD)
                    : (d_xBC0[dir] + (size_t)(b * 4 + t) * CONVD);
}
__device__ __forceinline__ float fast_silu(float x) {
    return __fdividef(x, 1.f + __expf(-x));
}

// f32x2 packed math (sm_100+)
#define MUL2(d, a, b) asm("mul.rn.f32x2 %0,%1,%2;" : "=l"(d) : "l"(a), "l"(b))
#define FMA2(d, a, b, c) asm("fma.rn.f32x2 %0,%1,%2,%3;" : "=l"(d) : "l"(a), "l"(b), "l"(c))
#define ADD2(d, a, b) asm("add.rn.f32x2 %0,%1,%2;" : "=l"(d) : "l"(a), "l"(b))
__device__ __forceinline__ unsigned long long pack2(float x) {
    unsigned long long r;
    asm("mov.b64 %0,{%1,%1};" : "=l"(r) : "r"(__float_as_uint(x)));
    return r;
}
__device__ __forceinline__ float sum2(unsigned long long v) {
    unsigned int lo, hi;
    asm("mov.b64 {%0,%1},%2;" : "=r"(lo), "=r"(hi) : "l"(v));
    return __uint_as_float(lo) + __uint_as_float(hi);
}

// ------------------------- 1. feature rows (2056 x 384) ----------------------
__global__ void feat_kernel(const int* __restrict__ pidx,
                            const int* __restrict__ chridx,
                            const float* __restrict__ locus_fourier,
                            const float* __restrict__ pathway,
                            const float* __restrict__ pert_emb,
                            const float* __restrict__ gene_id,
                            const float* __restrict__ chr_emb,
                            const float* __restrict__ locus_w,
                            const float* __restrict__ locus_b,
                            const float* __restrict__ cond_w,
                            const float* __restrict__ cond_b) {
    int g = blockIdx.x;
    int tid = threadIdx.x;  // 128
    if (g < 2048) {
        d_feat[g * GENEF + tid] = gene_id[g * 128 + tid];
        d_feat[g * GENEF + 128 + tid] = pathway[g * 128 + tid];
        if (tid < 64) {
            int ci = chridx[g];
            d_feat[g * GENEF + 256 + tid] = chr_emb[ci * 64 + tid];
        } else {
            int j = tid - 64;
            float acc = locus_b[j];
            const float* lf = locus_fourier + g * 64;
            const float* lw = locus_w + j * 64;
            for (int k = 0; k < 64; k++) acc = fmaf(lf[k], lw[k], acc);
            float ge = 0.5f * acc * (1.f + erff(acc * 0.70710678118654752f));
            d_feat[g * GENEF + 320 + j] = ge;
        }
    } else {
        int b = g - 2048;
        const float* pe = pert_emb + (size_t)pidx[b] * 128;
        for (int j = tid; j < GENEF; j += 128) {
            float acc = cond_b[j];
            const float* cw = cond_w + (size_t)j * 128;
            for (int k = 0; k < 128; k++) acc = fmaf(pe[k], cw[k], acc);
            d_feat[g * GENEF + j] = acc;
        }
    }
}

// ------------------------- 2. SGEMM 128x128 tile, 8x8/thread -----------------
__global__ __launch_bounds__(256) void sgemm128(int src_sel,
                                                const float* __restrict__ W,
                                                const float* __restrict__ bias,
                                                int dst_sel, int M, int N, int K) {
    const float* A = (src_sel == 0) ? d_feat : d_X;
    float* C = (dst_sel == 0) ? d_X : d_Z[dst_sel - 1];

    __shared__ __align__(16) float As[2][8][132];
    __shared__ __align__(16) float Ws[2][8][132];

    int tid = threadIdx.x;
    int row0 = blockIdx.y * 128, col0 = blockIdx.x * 128;
    int lr = tid >> 1;         // 0..127
    int lk = (tid & 1) * 4;    // 0 or 4
    bool aval = (row0 + lr) < M;
    bool wval = (col0 + lr) < N;
    const float* Aptr = A + (size_t)(row0 + lr) * K + lk;
    const float* Wptr = W + (size_t)(col0 + lr) * K + lk;

    float4 av = aval ? *(const float4*)Aptr : make_float4(0, 0, 0, 0);
    float4 wv = wval ? *(const float4*)Wptr : make_float4(0, 0, 0, 0);
    As[0][lk + 0][lr] = av.x; As[0][lk + 1][lr] = av.y;
    As[0][lk + 2][lr] = av.z; As[0][lk + 3][lr] = av.w;
    Ws[0][lk + 0][lr] = wv.x; Ws[0][lk + 1][lr] = wv.y;
    Ws[0][lk + 2][lr] = wv.z; Ws[0][lk + 3][lr] = wv.w;
    __syncthreads();

    float acc[8][8] = {};
    int ty = tid >> 4, tx = tid & 15;

    for (int k0 = 0; k0 < K; k0 += 8) {
        int buf = (k0 >> 3) & 1;
        bool more = (k0 + 8) < K;
        if (more) {
            av = aval ? *(const float4*)(Aptr + k0 + 8) : make_float4(0, 0, 0, 0);
            wv = wval ? *(const float4*)(Wptr + k0 + 8) : make_float4(0, 0, 0, 0);
        }
#pragma unroll
        for (int kk = 0; kk < 8; kk++) {
            float ra[8], rb[8];
#pragma unroll
            for (int i = 0; i < 8; i++) ra[i] = As[buf][kk][ty * 8 + i];
#pragma unroll
            for (int i = 0; i < 8; i++) rb[i] = Ws[buf][kk][tx * 8 + i];
#pragma unroll
            for (int i = 0; i < 8; i++)
#pragma unroll
                for (int j = 0; j < 8; j++)
                    acc[i][j] = fmaf(ra[i], rb[j], acc[i][j]);
        }
        if (more) {
            int nb = buf ^ 1;
            As[nb][lk + 0][lr] = av.x; As[nb][lk + 1][lr] = av.y;
            As[nb][lk + 2][lr] = av.z; As[nb][lk + 3][lr] = av.w;
            Ws[nb][lk + 0][lr] = wv.x; Ws[nb][lk + 1][lr] = wv.y;
            Ws[nb][lk + 2][lr] = wv.z; Ws[nb][lk + 3][lr] = wv.w;
        }
        __syncthreads();
    }
#pragma unroll
    for (int i = 0; i < 8; i++) {
        int r = row0 + ty * 8 + i;
        if (r >= M) continue;
#pragma unroll
        for (int j = 0; j < 8; j++) {
            int c = col0 + tx * 8 + j;
            if (c < N) C[(size_t)r * N + c] = acc[i][j] + (bias ? bias[c] : 0.f);
        }
    }
}

// ------------------------- 3. causal depthwise conv + silu -------------------
// shared part: one copy per (dir,t) for t>=4; per-batch part for t<4
__global__ void conv_kernel(const float* __restrict__ cw_f, const float* __restrict__ cb_f,
                            const float* __restrict__ cw_b, const float* __restrict__ cb_b) {
    int bx = blockIdx.x;
    int dir = blockIdx.y;
    const float* cw = dir ? cw_b : cw_f;
    const float* cb = dir ? cb_b : cb_f;
    const float* Z = d_Z[dir];

    const float* rows[4];
    float* dst;
    if (bx < L_SEQ) {
        int t = bx;
        if (t < 4) return;
        dst = d_xBCs[dir] + (size_t)t * CONVD;
#pragma unroll
        for (int k = 0; k < 4; k++) {
            int tau = dir ? (t + 3 - k) : (t - 3 + k);
            rows[k] = (tau <= L_SEQ - 1) ? (Z + (size_t)(tau - 1) * DPROJ + DIN) : nullptr;
        }
    } else {
        int idx = bx - L_SEQ;   // 0..31
        int b = idx >> 2;
        int t = idx & 3;
        dst = d_xBC0[dir] + (size_t)(b * 4 + t) * CONVD;
#pragma unroll
        for (int k = 0; k < 4; k++) {
            int tau = dir ? (t + 3 - k) : (t - 3 + k);
            rows[k] = (tau >= 0 && tau <= L_SEQ - 1)
                          ? (Z + (size_t)seq_row(b, tau) * DPROJ + DIN)
                          : nullptr;
        }
    }
    for (int c = threadIdx.x; c < CONVD; c += blockDim.x) {
        float acc = cb[c];
#pragma unroll
        for (int k = 0; k < 4; k++)
            if (rows[k]) acc = fmaf(rows[k][c], cw[c * 4 + k], acc);
        dst[c] = fast_silu(acc);
    }
}

// ------------------------- 4. dt / dA per row --------------------------------
__global__ void dtda_kernel(const float* __restrict__ fdtb, const float* __restrict__ fAl,
                            const float* __restrict__ bdtb, const float* __restrict__ bAl) {
    int idx = blockIdx.x * blockDim.x + threadIdx.x;
    const int per = NROWS * NH;
    if (idx >= 2 * per) return;
    int dir = idx / per;
    int r = idx % per;
    int row = r >> 4;
    int h = r & 15;
    float raw = d_Z[dir][(size_t)row * DPROJ + (DIN + CONVD) + h] + (dir ? bdtb : fdtb)[h];
    float dtv = (raw > 20.f) ? raw : log1pf(expf(raw));
    float Al = (dir ? bAl : fAl)[h];
    d_dtr[dir][row * NH + h] = dtv;
    d_dAr[dir][row * NH + h] = expf(-expf(Al) * dtv);
}

// ------------------------- 5. combined output vector -------------------------
__global__ void wcomb_kernel(const float* __restrict__ head_w,
                             const float* __restrict__ fow, const float* __restrict__ bow,
                             const float* __restrict__ fnw, const float* __restrict__ bnw) {
    int idx = blockIdx.x * blockDim.x + threadIdx.x;
    if (idx >= 2 * DIN) return;
    int dir = idx >> 10;
    int j = idx & 1023;
    const float* ow = dir ? bow : fow;
    float acc = 0.f;
    for (int i = 0; i < DMODEL; i++) acc = fmaf(ow[(size_t)i * DIN + j], head_w[i], acc);
    d_wcomb[dir][j] = acc * (dir ? bnw : fnw)[j];
}

// ------------------------- 5b. silu(z) per gene row --------------------------
__global__ void siluz_kernel() {
    int row = blockIdx.x;   // 0..2047
    int dir = blockIdx.y;
    const float* z = d_Z[dir] + (size_t)row * DPROJ;
    float* P = d_P[dir] + (size_t)row * DIN;
    for (int j = threadIdx.x; j < DIN; j += 256) P[j] = fast_silu(z[j]);
}

// ------------------------- 6. sequential SSM scan ----------------------------
// block = (dir,b,h); 128 threads; thread owns p = tid&63, n-half nh = tid>>6
// pipelined: 1 barrier/step, double-buffered shared, f32x2 math
__global__ __launch_bounds__(128) void scan_kernel(const float* __restrict__ fD,
                                                   const float* __restrict__ bD) {
    int blk = blockIdx.x;
    int dir = blk >> 7;
    int bh = blk & 127;
    int b = bh >> 4;
    int h = bh & 15;
    float Dh = (dir ? bD : fD)[h];
    const float* dtr = d_dtr[dir];
    const float* dAr = d_dAr[dir];
    float* yp = d_yp[dir];

    int tid = threadIdx.x;
    int p = tid & 63;
    int nh = tid >> 6;

    __shared__ __align__(16) float sB[2][128], sC[2][128], sx[2][64];

    unsigned long long hs2[32];
#pragma unroll
    for (int i = 0; i < 32; i++) hs2[i] = 0ull;

    int t0 = dir ? (L_SEQ - 1) : 0;
    const float* pp = xbc_ptr(dir, b, t0);
    float rB = pp[DIN + tid];
    float rC = pp[DIN + NS + tid];
    float rx = (tid < 64) ? pp[h * HD + tid] : 0.f;
    int row0 = (t0 == 0) ? (2048 + b) : (t0 - 1);
    float rdt = dtr[row0 * NH + h];
    float rdA = dAr[row0 * NH + h];

    for (int s = 0; s < L_SEQ; s++) {
        int buf = s & 1;
        int t = dir ? (L_SEQ - 1 - s) : s;
        sB[buf][tid] = rB;
        sC[buf][tid] = rC;
        if (tid < 64) sx[buf][tid] = rx;
        float dtv = rdt, dAv = rdA;
        __syncthreads();

        // prefetch step s+1 (clamped harmless reload on last step)
        int sn = (s + 1 < L_SEQ) ? (s + 1) : s;
        int tn = dir ? (L_SEQ - 1 - sn) : sn;
        const float* pn = xbc_ptr(dir, b, tn);
        rB = pn[DIN + tid];
        rC = pn[DIN + NS + tid];
        if (tid < 64) rx = pn[h * HD + tid];
        int rown = (tn == 0) ? (2048 + b) : (tn - 1);
        rdt = dtr[rown * NH + h];
        rdA = dAr[rown * NH + h];

        // compute
        float coef = dtv * sx[buf][p];
        unsigned long long coef2 = pack2(coef);
        unsigned long long dA2 = pack2(dAv);
        const unsigned long long* B2 = (const unsigned long long*)(sB[buf] + nh * 64);
        const unsigned long long* C2 = (const unsigned long long*)(sC[buf] + nh * 64);
        unsigned long long a0 = 0ull, a1 = 0ull, a2 = 0ull, a3 = 0ull;
#pragma unroll
        for (int i = 0; i < 32; i += 4) {
            unsigned long long tm;
            MUL2(tm, coef2, B2[i]);
            FMA2(hs2[i], dA2, hs2[i], tm);
            FMA2(a0, hs2[i], C2[i], a0);
            MUL2(tm, coef2, B2[i + 1]);
            FMA2(hs2[i + 1], dA2, hs2[i + 1], tm);
            FMA2(a1, hs2[i + 1], C2[i + 1], a1);
            MUL2(tm, coef2, B2[i + 2]);
            FMA2(hs2[i + 2], dA2, hs2[i + 2], tm);
            FMA2(a2, hs2[i + 2], C2[i + 2], a2);
            MUL2(tm, coef2, B2[i + 3]);
            FMA2(hs2[i + 3], dA2, hs2[i + 3], tm);
            FMA2(a3, hs2[i + 3], C2[i + 3], a3);
        }
        ADD2(a0, a0, a1);
        ADD2(a2, a2, a3);
        ADD2(a0, a0, a2);
        float part = sum2(a0);
        if (nh == 0) part = fmaf(Dh, sx[buf][p], part);
        size_t rb = (size_t)(b * L_SEQ + t);
        yp[(rb * NH + h) * 128 + tid] = part;
    }
}

// ------------------------- 7. gate + RMSnorm + fused head --------------------
__global__ __launch_bounds__(256) void final_kernel(const float* __restrict__ head_b,
                                                    float* __restrict__ out) {
    int blk = blockIdx.x;       // 0..8*2048-1
    int b = blk >> 11;
    int t = (blk & 2047) + 1;
    int tid = threadIdx.x;      // 256
    int zrow = t - 1;
    __shared__ float sh1[8], sh2[8];
    float resv = 0.f;
    for (int dir = 0; dir < 2; dir++) {
        const float* yp = d_yp[dir] + ((size_t)(b * L_SEQ + t) * NH) * 128;
        const float* P = d_P[dir] + (size_t)zrow * DIN;
        const float* wc = d_wcomb[dir];
        float ssq = 0.f, sdot = 0.f;
        for (int j = tid; j < DIN; j += 256) {
            int hh = j >> 6, ppp = j & 63;
            float yv = yp[hh * 128 + ppp] + yp[hh * 128 + 64 + ppp];
            float g = yv * P[j];
            ssq = fmaf(g, g, ssq);
            sdot = fmaf(g, wc[j], sdot);
        }
#pragma unroll
        for (int off = 16; off; off >>= 1) {
            ssq += __shfl_xor_sync(0xffffffffu, ssq, off);
            sdot += __shfl_xor_sync(0xffffffffu, sdot, off);
        }
        int w = tid >> 5, l = tid & 31;
        if (l == 0) { sh1[w] = ssq; sh2[w] = sdot; }
        __syncthreads();
        if (tid == 0) {
            float A = 0.f, Bt = 0.f;
            for (int i = 0; i < 8; i++) { A += sh1[i]; Bt += sh2[i]; }
            resv += rsqrtf(A * (1.f / 1024.f) + 1e-5f) * Bt;
        }
        __syncthreads();
    }
    if (tid == 0) out[blk] = resv + head_b[0];
}

// ------------------------- launch --------------------------------------------
extern "C" void kernel_launch(void* const* d_in, const int* in_sizes, int n_in,
                              void* d_out, int out_size) {
    const int* pidx            = (const int*)d_in[0];
    const int* chridx          = (const int*)d_in[1];
    const float* locus_fourier = (const float*)d_in[2];
    const float* pathway       = (const float*)d_in[3];
    const float* pert_emb      = (const float*)d_in[4];
    const float* gene_id       = (const float*)d_in[5];
    const float* chr_emb       = (const float*)d_in[6];
    const float* locus_w       = (const float*)d_in[7];
    const float* locus_b       = (const float*)d_in[8];
    const float* cond_w        = (const float*)d_in[9];
    const float* cond_b        = (const float*)d_in[10];
    const float* in_w          = (const float*)d_in[11];
    const float* in_b          = (const float*)d_in[12];
    const float* head_w        = (const float*)d_in[13];
    const float* head_b        = (const float*)d_in[14];
    const float* f_in_w        = (const float*)d_in[15];
    const float* f_conv_w      = (const float*)d_in[16];
    const float* f_conv_b      = (const float*)d_in[17];
    const float* f_dt_bias     = (const float*)d_in[18];
    const float* f_A_log       = (const float*)d_in[19];
    const float* f_D           = (const float*)d_in[20];
    const float* f_norm_w      = (const float*)d_in[21];
    const float* f_out_w       = (const float*)d_in[22];
    const float* b_in_w        = (const float*)d_in[23];
    const float* b_conv_w      = (const float*)d_in[24];
    const float* b_conv_b      = (const float*)d_in[25];
    const float* b_dt_bias     = (const float*)d_in[26];
    const float* b_A_log       = (const float*)d_in[27];
    const float* b_D           = (const float*)d_in[28];
    const float* b_norm_w      = (const float*)d_in[29];
    const float* b_out_w       = (const float*)d_in[30];
    float* out = (float*)d_out;

    feat_kernel<<<NROWS, 128>>>(pidx, chridx, locus_fourier, pathway, pert_emb,
                                gene_id, chr_emb, locus_w, locus_b, cond_w, cond_b);

    // X = feat @ in_w^T + in_b  (2056 x 512, K=384)
    sgemm128<<<dim3(4, 17), 256>>>(0, in_w, in_b, 0, NROWS, DMODEL, GENEF);
    // Z_dir = X @ {f,b}_in_w^T  (2056 x 2320, K=512)
    sgemm128<<<dim3(19, 17), 256>>>(1, f_in_w, nullptr, 1, NROWS, DPROJ, DMODEL);
    sgemm128<<<dim3(19, 17), 256>>>(1, b_in_w, nullptr, 2, NROWS, DPROJ, DMODEL);

    // depthwise conv + silu (batch-shared for t>=4, per-batch patch for t<4)
    conv_kernel<<<dim3(L_SEQ + 32, 2), 256>>>(f_conv_w, f_conv_b, b_conv_w, b_conv_b);

    // dt / dA per row
    dtda_kernel<<<(2 * NROWS * NH + 255) / 256, 256>>>(f_dt_bias, f_A_log, b_dt_bias, b_A_log);

    // combined head vector and silu(z) precompute
    wcomb_kernel<<<(2 * DIN + 255) / 256, 256>>>(head_w, f_out_w, b_out_w, f_norm_w, b_norm_w);
    siluz_kernel<<<dim3(2048, 2), 256>>>();

    // sequential scan (both dirs concurrently)
    scan_kernel<<<256, 128>>>(f_D, b_D);

    // gate + RMSnorm + fused output head
    final_kernel<<<BATCH * 2048, 256>>>(head_b, out);
}